// round 9
// baseline (speedup 1.0000x reference)
#include <cuda_runtime.h>
#include <cuda_bf16.h>

#define NN   50000
#define NE   1600000
#define NR   8
#define KC   1152        // NR*128 + 128
#define CAP  16384
#define NP   256
#define DOUT 64

// ---- scratch (zero-initialized once by CUDA) ----
__device__ int   g_pmap[NN];          // 1 = pooled dst (idempotent across runs)
__device__ int   g_nf[NN];            // 1 = needed node (idempotent across runs)
__device__ int   g_cid[NN];
__device__ int   g_nodes[CAP];
__device__ int   g_counter;           // reset each run in k_mark_pool
__device__ unsigned g_done;           // pool-block ticket; last block resets to 0
__device__ int   g_head[NR * NN];     // head = edge+1, 0 = empty; CLEARED each run
__device__ int   g_next[NE];          // next pointer (edge+1 or 0), rewritten each run
__device__ __align__(16) __nv_bfloat16 g_Ahi[(size_t)CAP * KC];
__device__ __align__(16) __nv_bfloat16 g_Alo[(size_t)CAP * KC];
__device__ __align__(16) __nv_bfloat16 g_Bhi[128 * KC];   // [outcol h][k]
__device__ __align__(16) __nv_bfloat16 g_Blo[128 * KC];
__device__ float g_h[(size_t)CAP * 128];
__device__ float g_part[NP * DOUT];
__device__ float g_wp[NP];

static __device__ __forceinline__ void split2(float v, __nv_bfloat16& hi, __nv_bfloat16& lo) {
    hi = __float2bfloat16_rn(v);
    lo = __float2bfloat16_rn(v - __bfloat162float(hi));
}

// warp mma m16n8k16 bf16 -> f32 accum (baseline PTX, HMMA on sm_103)
#define MMA16816(c, a, b) \
    asm volatile("mma.sync.aligned.m16n8k16.row.col.f32.bf16.bf16.f32 " \
                 "{%0,%1,%2,%3},{%4,%5,%6,%7},{%8,%9},{%0,%1,%2,%3};" \
                 : "+f"((c)[0]), "+f"((c)[1]), "+f"((c)[2]), "+f"((c)[3]) \
                 : "r"((a)[0]), "r"((a)[1]), "r"((a)[2]), "r"((a)[3]), \
                   "r"((b)[0]), "r"((b)[1]))

// ------------------------------------------- kernel 1: mark pool + resets
__global__ void k_mark_pool(const int* __restrict__ pool) {
    int p = pool[threadIdx.x];
    g_pmap[p] = 1;
    g_nf[p]   = 1;
    if (threadIdx.x == 0) { g_counter = 0; g_done = 0; }
}

// --------------------- kernel 2: mark_src || wsplit || head-clear
#define NB_MS ((NE + 255) / 256)
#define NB_WS ((128 * KC + 255) / 256)
#define NB_HC ((NR * NN / 4 + 255) / 256)    // clear as int4
__global__ void k_mark_ws(const int* __restrict__ ei,
                          const float* __restrict__ W1,
                          const float* __restrict__ root1) {
    int b = blockIdx.x;
    if (b < NB_MS) {
        int e = b * 256 + threadIdx.x;
        if (e < NE) {
            int dst = ei[NE + e];
            if (g_pmap[dst]) g_nf[ei[e]] = 1;
        }
    } else if (b < NB_MS + NB_WS) {
        int idx = (b - NB_MS) * 256 + threadIdx.x;   // 128*KC
        if (idx < 128 * KC) {
            int h = idx / KC, k = idx - h * KC;
            float w = (k < 1024) ? W1[k * 128 + h] : root1[(k - 1024) * 128 + h];
            __nv_bfloat16 hi, lo;
            split2(w, hi, lo);
            g_Bhi[idx] = hi;
            g_Blo[idx] = lo;
        }
    } else {
        int idx = (b - NB_MS - NB_WS) * 256 + threadIdx.x;   // int4 index
        if (idx < NR * NN / 4)
            ((int4*)g_head)[idx] = make_int4(0, 0, 0, 0);
    }
}

// ------------------------------------------- kernel 3: compact || build
#define NB_CP ((NN + 255) / 256)
__global__ void k_cb(const int* __restrict__ ei, const int* __restrict__ et) {
    int b = blockIdx.x;
    if (b < NB_CP) {
        int v = b * 256 + threadIdx.x;
        int lane = threadIdx.x & 31;
        int pred = (v < NN) && g_nf[v];
        unsigned mask = __ballot_sync(0xFFFFFFFF, pred);
        if (mask) {
            int leader = __ffs(mask) - 1;
            int base = 0;
            if (lane == leader) base = atomicAdd(&g_counter, __popc(mask));
            base = __shfl_sync(0xFFFFFFFF, base, leader);
            if (pred) {
                int c = base + __popc(mask & ((1u << lane) - 1));
                if (c < CAP) { g_cid[v] = c; g_nodes[c] = v; }
            }
        }
    } else {
        int e = (b - NB_CP) * 256 + threadIdx.x;
        if (e < NE) {
            int dst = ei[NE + e];
            if (g_nf[dst]) {
                int r = et[e];
                g_next[e] = atomicExch(&g_head[r * NN + dst], e + 1);
            }
        }
    }
}

// ------------------------------------------- kernel 4: layer-1 aggregation
// Warp-per-node: all 8 relation chains advanced round-robin -> MLP on the
// dependent g_next/ei/x loads instead of serial per-(node,rel) chases.
__global__ void __launch_bounds__(256) k_agg1(const float* __restrict__ x,
                                              const int* __restrict__ ei) {
    const float4* x4 = (const float4*)x;
    int wid   = (blockIdx.x * blockDim.x + threadIdx.x) >> 5;
    int lane  = threadIdx.x & 31;
    int nwarp = (gridDim.x * blockDim.x) >> 5;
    int cnt   = min(g_counter, CAP);

    for (int i = wid; i < cnt; i += nwarp) {
        int v = g_nodes[i];

        // self row (r == 8)
        {
            float4 sv = x4[v * 32 + lane];
            __nv_bfloat16 h[4], l[4];
            split2(sv.x, h[0], l[0]);
            split2(sv.y, h[1], l[1]);
            split2(sv.z, h[2], l[2]);
            split2(sv.w, h[3], l[3]);
            size_t off = (size_t)i * KC + 8 * 128 + lane * 4;
            *(uint2*)&g_Ahi[off] = *(uint2*)h;
            *(uint2*)&g_Alo[off] = *(uint2*)l;
        }

        int ptr[NR];
        int c[NR];
        float4 acc[NR];
#pragma unroll
        for (int r = 0; r < NR; r++) {
            ptr[r] = g_head[r * NN + v];
            c[r] = 0;
            acc[r] = make_float4(0.f, 0.f, 0.f, 0.f);
        }

        bool any = false;
#pragma unroll
        for (int r = 0; r < NR; r++) any |= (ptr[r] != 0);

        while (any) {
            int e[NR], src[NR], nxt[NR];
            // issue all chain loads first (independent -> overlapped)
#pragma unroll
            for (int r = 0; r < NR; r++) {
                if (ptr[r]) {
                    e[r]   = ptr[r] - 1;
                    src[r] = ei[e[r]];
                    nxt[r] = g_next[e[r]];
                }
            }
            // gathers (8-way MLP)
#pragma unroll
            for (int r = 0; r < NR; r++) {
                if (ptr[r]) {
                    float4 xv = x4[src[r] * 32 + lane];
                    acc[r].x += xv.x; acc[r].y += xv.y;
                    acc[r].z += xv.z; acc[r].w += xv.w;
                    c[r]++;
                    ptr[r] = nxt[r];
                }
            }
            any = false;
#pragma unroll
            for (int r = 0; r < NR; r++) any |= (ptr[r] != 0);
        }

#pragma unroll
        for (int r = 0; r < NR; r++) {
            float4 a = acc[r];
            if (c[r] > 1) {
                float s = 1.0f / (float)c[r];
                a.x *= s; a.y *= s; a.z *= s; a.w *= s;
            }
            __nv_bfloat16 h[4], l[4];
            split2(a.x, h[0], l[0]);
            split2(a.y, h[1], l[1]);
            split2(a.z, h[2], l[2]);
            split2(a.w, h[3], l[3]);
            size_t off = (size_t)i * KC + r * 128 + lane * 4;
            *(uint2*)&g_Ahi[off] = *(uint2*)h;
            *(uint2*)&g_Alo[off] = *(uint2*)l;
        }
    }
}

// ------------------------------------------- kernel 5: layer-1 GEMM (HMMA)
#define SA 40
__global__ void __launch_bounds__(256) k_gemm1h(const float* __restrict__ b1) {
    __shared__ __align__(16) __nv_bfloat16 As[2][64 * SA];
    __shared__ __align__(16) __nv_bfloat16 Bs[2][128 * SA];
    int cnt  = min(g_counter, CAP);
    int row0 = blockIdx.x * 64;
    if (row0 >= cnt) return;
    int t = threadIdx.x;
    int lane = t & 31, wid = t >> 5;
    int wm = (wid & 1) * 32;
    int wn = (wid >> 1) * 32;
    int gr4 = lane >> 2;
    int kc  = (lane & 3) * 2;

    float acc[2][4][4];
#pragma unroll
    for (int mt = 0; mt < 2; mt++)
#pragma unroll
        for (int nt = 0; nt < 4; nt++)
#pragma unroll
            for (int j = 0; j < 4; j++) acc[mt][nt][j] = 0.f;

    for (int c = 0; c < KC / 32; c++) {
        {
            int row = t >> 2, q = t & 3;
            int gr = row0 + row;
            uint4 vh = make_uint4(0u, 0u, 0u, 0u), vl = vh;
            if (gr < cnt) {
                size_t s = (size_t)gr * KC + c * 32 + q * 8;
                vh = *(const uint4*)&g_Ahi[s];
                vl = *(const uint4*)&g_Alo[s];
            }
            *(uint4*)&As[0][row * SA + q * 8] = vh;
            *(uint4*)&As[1][row * SA + q * 8] = vl;
        }
#pragma unroll
        for (int q2 = 0; q2 < 2; q2++) {
            int idx = t + q2 * 256;
            int h = idx >> 2, q = idx & 3;
            size_t s = (size_t)h * KC + c * 32 + q * 8;
            *(uint4*)&Bs[0][h * SA + q * 8] = *(const uint4*)&g_Bhi[s];
            *(uint4*)&Bs[1][h * SA + q * 8] = *(const uint4*)&g_Blo[s];
        }
        __syncthreads();

#pragma unroll
        for (int ks = 0; ks < 32; ks += 16) {
            unsigned ah[2][4], al[2][4], bh[4][2], bl[4][2];
#pragma unroll
            for (int mt = 0; mt < 2; mt++) {
                int r0 = wm + mt * 16 + gr4;
                ah[mt][0] = *(const unsigned*)&As[0][(r0    ) * SA + ks + kc];
                ah[mt][1] = *(const unsigned*)&As[0][(r0 + 8) * SA + ks + kc];
                ah[mt][2] = *(const unsigned*)&As[0][(r0    ) * SA + ks + kc + 8];
                ah[mt][3] = *(const unsigned*)&As[0][(r0 + 8) * SA + ks + kc + 8];
                al[mt][0] = *(const unsigned*)&As[1][(r0    ) * SA + ks + kc];
                al[mt][1] = *(const unsigned*)&As[1][(r0 + 8) * SA + ks + kc];
                al[mt][2] = *(const unsigned*)&As[1][(r0    ) * SA + ks + kc + 8];
                al[mt][3] = *(const unsigned*)&As[1][(r0 + 8) * SA + ks + kc + 8];
            }
#pragma unroll
            for (int nt = 0; nt < 4; nt++) {
                int n0 = wn + nt * 8 + gr4;
                bh[nt][0] = *(const unsigned*)&Bs[0][n0 * SA + ks + kc];
                bh[nt][1] = *(const unsigned*)&Bs[0][n0 * SA + ks + kc + 8];
                bl[nt][0] = *(const unsigned*)&Bs[1][n0 * SA + ks + kc];
                bl[nt][1] = *(const unsigned*)&Bs[1][n0 * SA + ks + kc + 8];
            }
#pragma unroll
            for (int mt = 0; mt < 2; mt++)
#pragma unroll
                for (int nt = 0; nt < 4; nt++) {
                    MMA16816(acc[mt][nt], ah[mt], bh[nt]);
                    MMA16816(acc[mt][nt], al[mt], bh[nt]);
                    MMA16816(acc[mt][nt], ah[mt], bl[nt]);
                }
        }
        __syncthreads();
    }

#pragma unroll
    for (int mt = 0; mt < 2; mt++) {
#pragma unroll
        for (int nt = 0; nt < 4; nt++) {
            int col = wn + nt * 8 + kc;
            float b0 = b1[col], b1v = b1[col + 1];
            int r0 = row0 + wm + mt * 16 + gr4;
            int r1 = r0 + 8;
            if (r0 < cnt) {
                float2 o;
                o.x = fmaxf(acc[mt][nt][0] + b0, 0.f);
                o.y = fmaxf(acc[mt][nt][1] + b1v, 0.f);
                *(float2*)&g_h[(size_t)r0 * 128 + col] = o;
            }
            if (r1 < cnt) {
                float2 o;
                o.x = fmaxf(acc[mt][nt][2] + b0, 0.f);
                o.y = fmaxf(acc[mt][nt][3] + b1v, 0.f);
                *(float2*)&g_h[(size_t)r1 * 128 + col] = o;
            }
        }
    }
}

// ------------------------------------------- kernel 6: layer-2 + pool + final
__global__ void __launch_bounds__(256) k_pool(const float* __restrict__ x,
                                              const int* __restrict__ pool,
                                              const int* __restrict__ ei,
                                              const float* __restrict__ W2,
                                              const float* __restrict__ root2,
                                              const float* __restrict__ b2,
                                              float* __restrict__ out) {
    __shared__ float cs[KC];
    __shared__ float red[256];
    __shared__ unsigned s_ticket;
    const float4* h4 = (const float4*)g_h;
    int p = pool[blockIdx.x];
    int t = threadIdx.x;
    int lane = t & 31, w = t >> 5;

    {
        int r = w;
        int ptr = g_head[r * NN + p];
        int c = 0;
        float4 acc = make_float4(0.f, 0.f, 0.f, 0.f);
        while (ptr) {
            int e = ptr - 1;
            int src = ei[e];
            int ci = g_cid[src];
            float4 hv = h4[ci * 32 + lane];
            acc.x += hv.x; acc.y += hv.y; acc.z += hv.z; acc.w += hv.w;
            c++;
            ptr = g_next[e];
        }
        if (c > 1) {
            float s = 1.0f / (float)c;
            acc.x *= s; acc.y *= s; acc.z *= s; acc.w *= s;
        }
        *(float4*)&cs[r * 128 + lane * 4] = acc;
    }
    if (t < 128) {
        int cp = g_cid[p];
        cs[1024 + t] = g_h[(size_t)cp * 128 + t];
    }
    __syncthreads();

    int j = t & 63, q = t >> 6;
    float s = 0.f;
    int k0 = q * 288;
#pragma unroll 4
    for (int k = k0; k < k0 + 288; k++) {
        float wv = (k < 1024) ? W2[k * 64 + j] : root2[(k - 1024) * 64 + j];
        s += cs[k] * wv;
    }
    red[t] = s;
    __syncthreads();
    if (t < 64) {
        float o = red[t] + red[t + 64] + red[t + 128] + red[t + 192] + b2[j];
        float wp = 4.f * x[p * 128 + 0] + x[p * 128 + 1] + 2.f * x[p * 128 + 2];
        g_part[blockIdx.x * 64 + j] = o * wp;
        if (j == 0) g_wp[blockIdx.x] = wp;
    }

    // ---- last-block final reduction ----
    __threadfence();
    __syncthreads();
    if (t == 0) s_ticket = atomicAdd(&g_done, 1);
    __syncthreads();
    if (s_ticket == NP - 1) {
        __threadfence();
        if (t < 64) {
            float acc = 0.f;
            for (int i = 0; i < NP; i++) acc += g_part[i * 64 + t];
            float ws = 0.f;
            for (int i = 0; i < NP; i++) ws += g_wp[i];
            out[t] = acc / (ws + 1e-9f);
        }
        if (t == 0) g_done = 0;   // reset for next replay
    }
}

// ---------------------------------------------------------------- launch
extern "C" void kernel_launch(void* const* d_in, const int* in_sizes, int n_in,
                              void* d_out, int out_size) {
    const float* x     = (const float*)d_in[0];
    const int*   ei    = (const int*)  d_in[1];
    const int*   et    = (const int*)  d_in[2];
    const int*   pool  = (const int*)  d_in[3];
    const float* W1    = (const float*)d_in[4];
    const float* root1 = (const float*)d_in[5];
    const float* b1    = (const float*)d_in[6];
    const float* W2    = (const float*)d_in[7];
    const float* root2 = (const float*)d_in[8];
    const float* b2    = (const float*)d_in[9];
    float* out = (float*)d_out;
    (void)in_sizes; (void)n_in; (void)out_size;

    k_mark_pool<<<1, NP>>>(pool);
    k_mark_ws  <<<NB_MS + NB_WS + NB_HC, 256>>>(ei, W1, root1);
    k_cb       <<<NB_CP + NB_MS, 256>>>(ei, et);
    k_agg1     <<<1024, 256>>>(x, ei);
    k_gemm1h   <<<CAP / 64, 256>>>(b1);
    k_pool     <<<NP, 256>>>(x, pool, ei, W2, root2, b2, out);
}

// round 10
// speedup vs baseline: 1.1757x; 1.1757x over previous
#include <cuda_runtime.h>
#include <cuda_bf16.h>

#define NN   50000
#define NE   1600000
#define NR   8
#define KC   1152        // NR*128 + 128
#define CAP  16384
#define NP   256
#define DOUT 64

// ---- scratch (zero-initialized once by CUDA) ----
__device__ int   g_pmap[NN];          // 1 = pooled dst (idempotent across runs)
__device__ int   g_nf[NN];            // 1 = needed node (idempotent across runs)
__device__ int   g_cid[NN];
__device__ int   g_nodes[CAP];
__device__ int   g_counter;           // reset each run in k_mark_pool
__device__ unsigned g_done;           // pool-block ticket; last block resets to 0
__device__ int   g_head[NR * NN];     // head = edge+1, 0 = empty; CLEARED each run
__device__ int   g_next[NE];          // next pointer (edge+1 or 0), rewritten each run
__device__ __align__(16) __nv_bfloat16 g_Ahi[(size_t)CAP * KC];
__device__ __align__(16) __nv_bfloat16 g_Alo[(size_t)CAP * KC];
__device__ __align__(16) __nv_bfloat16 g_Bhi[128 * KC];   // [outcol h][k]
__device__ __align__(16) __nv_bfloat16 g_Blo[128 * KC];
__device__ float g_h[(size_t)CAP * 128];
__device__ float g_part[NP * DOUT];
__device__ float g_wp[NP];

static __device__ __forceinline__ void split2(float v, __nv_bfloat16& hi, __nv_bfloat16& lo) {
    hi = __float2bfloat16_rn(v);
    lo = __float2bfloat16_rn(v - __bfloat162float(hi));
}

// warp mma m16n8k16 bf16 -> f32 accum (baseline PTX, HMMA on sm_103)
#define MMA16816(c, a, b) \
    asm volatile("mma.sync.aligned.m16n8k16.row.col.f32.bf16.bf16.f32 " \
                 "{%0,%1,%2,%3},{%4,%5,%6,%7},{%8,%9},{%0,%1,%2,%3};" \
                 : "+f"((c)[0]), "+f"((c)[1]), "+f"((c)[2]), "+f"((c)[3]) \
                 : "r"((a)[0]), "r"((a)[1]), "r"((a)[2]), "r"((a)[3]), \
                   "r"((b)[0]), "r"((b)[1]))

// ------------------------------------------- kernel 1: mark pool + resets
__global__ void k_mark_pool(const int* __restrict__ pool) {
    int p = pool[threadIdx.x];
    g_pmap[p] = 1;
    g_nf[p]   = 1;
    if (threadIdx.x == 0) { g_counter = 0; g_done = 0; }
}

// --------------------- kernel 2: mark_src || wsplit || head-clear
#define NB_MS ((NE + 255) / 256)
#define NB_WS ((128 * KC + 255) / 256)
#define NB_HC ((NR * NN / 4 + 255) / 256)    // clear as int4
__global__ void k_mark_ws(const int* __restrict__ ei,
                          const float* __restrict__ W1,
                          const float* __restrict__ root1) {
    int b = blockIdx.x;
    if (b < NB_MS) {
        int e = b * 256 + threadIdx.x;
        if (e < NE) {
            int dst = ei[NE + e];
            if (g_pmap[dst]) g_nf[ei[e]] = 1;
        }
    } else if (b < NB_MS + NB_WS) {
        int idx = (b - NB_MS) * 256 + threadIdx.x;   // 128*KC
        if (idx < 128 * KC) {
            int h = idx / KC, k = idx - h * KC;
            float w = (k < 1024) ? W1[k * 128 + h] : root1[(k - 1024) * 128 + h];
            __nv_bfloat16 hi, lo;
            split2(w, hi, lo);
            g_Bhi[idx] = hi;
            g_Blo[idx] = lo;
        }
    } else {
        int idx = (b - NB_MS - NB_WS) * 256 + threadIdx.x;   // int4 index
        if (idx < NR * NN / 4)
            ((int4*)g_head)[idx] = make_int4(0, 0, 0, 0);
    }
}

// ------------------------------------------- kernel 3: compact || build
#define NB_CP ((NN + 255) / 256)
__global__ void k_cb(const int* __restrict__ ei, const int* __restrict__ et) {
    int b = blockIdx.x;
    if (b < NB_CP) {
        int v = b * 256 + threadIdx.x;
        int lane = threadIdx.x & 31;
        int pred = (v < NN) && g_nf[v];
        unsigned mask = __ballot_sync(0xFFFFFFFF, pred);
        if (mask) {
            int leader = __ffs(mask) - 1;
            int base = 0;
            if (lane == leader) base = atomicAdd(&g_counter, __popc(mask));
            base = __shfl_sync(0xFFFFFFFF, base, leader);
            if (pred) {
                int c = base + __popc(mask & ((1u << lane) - 1));
                if (c < CAP) { g_cid[v] = c; g_nodes[c] = v; }
            }
        }
    } else {
        int e = (b - NB_CP) * 256 + threadIdx.x;
        if (e < NE) {
            int dst = ei[NE + e];
            if (g_nf[dst]) {
                int r = et[e];
                g_next[e] = atomicExch(&g_head[r * NN + dst], e + 1);
            }
        }
    }
}

// ------------------------------------------- kernel 4: layer-1 aggregation
// Task-per-warp (R8 shape, 76K tasks) with TWO tasks walked concurrently
// per warp: doubles chase MLP at ~+10 regs, keeps occupancy high.
__global__ void __launch_bounds__(256) k_agg1(const float* __restrict__ x,
                                              const int* __restrict__ ei) {
    const float4* x4 = (const float4*)x;
    int wid   = (blockIdx.x * blockDim.x + threadIdx.x) >> 5;
    int lane  = threadIdx.x & 31;
    int nwarp = (gridDim.x * blockDim.x) >> 5;
    int cnt   = min(g_counter, CAP);
    int ntask = cnt * 9;

    for (int base = wid * 2; base < ntask; base += nwarp * 2) {
        int    tid_ [2];
        int    ptr_ [2];
        int    c_   [2];
        float4 acc_ [2];
        bool   chain[2];
#pragma unroll
        for (int s = 0; s < 2; s++) {
            int tt = base + s;
            tid_[s] = tt;
            ptr_[s] = 0;
            c_[s]   = 0;
            acc_[s] = make_float4(0.f, 0.f, 0.f, 0.f);
            chain[s] = false;
            if (tt < ntask) {
                int i = tt / 9;
                int r = tt - i * 9;
                int v = g_nodes[i];
                if (r == 8) {
                    acc_[s] = x4[v * 32 + lane];   // self row
                } else {
                    ptr_[s] = g_head[r * NN + v];
                    chain[s] = true;
                }
            }
        }

        // walk both chains concurrently (independent -> 2-way MLP on hops)
        while (ptr_[0] | ptr_[1]) {
            int src[2], nxt[2];
#pragma unroll
            for (int s = 0; s < 2; s++) {
                if (ptr_[s]) {
                    int e = ptr_[s] - 1;
                    src[s] = ei[e];
                    nxt[s] = g_next[e];
                }
            }
#pragma unroll
            for (int s = 0; s < 2; s++) {
                if (ptr_[s]) {
                    float4 xv = x4[src[s] * 32 + lane];
                    acc_[s].x += xv.x; acc_[s].y += xv.y;
                    acc_[s].z += xv.z; acc_[s].w += xv.w;
                    c_[s]++;
                    ptr_[s] = nxt[s];
                }
            }
        }

#pragma unroll
        for (int s = 0; s < 2; s++) {
            int tt = tid_[s];
            if (tt >= ntask) continue;
            int i = tt / 9;
            int r = tt - i * 9;
            float4 a = acc_[s];
            if (chain[s] && c_[s] > 1) {
                float sc = 1.0f / (float)c_[s];
                a.x *= sc; a.y *= sc; a.z *= sc; a.w *= sc;
            }
            __nv_bfloat16 h[4], l[4];
            split2(a.x, h[0], l[0]);
            split2(a.y, h[1], l[1]);
            split2(a.z, h[2], l[2]);
            split2(a.w, h[3], l[3]);
            size_t off = (size_t)i * KC + r * 128 + lane * 4;
            *(uint2*)&g_Ahi[off] = *(uint2*)h;
            *(uint2*)&g_Alo[off] = *(uint2*)l;
        }
    }
}

// ------------------------------------------- kernel 5: layer-1 GEMM (HMMA)
#define SA 40
__global__ void __launch_bounds__(256) k_gemm1h(const float* __restrict__ b1) {
    __shared__ __align__(16) __nv_bfloat16 As[2][64 * SA];
    __shared__ __align__(16) __nv_bfloat16 Bs[2][128 * SA];
    int cnt  = min(g_counter, CAP);
    int row0 = blockIdx.x * 64;
    if (row0 >= cnt) return;
    int t = threadIdx.x;
    int lane = t & 31, wid = t >> 5;
    int wm = (wid & 1) * 32;
    int wn = (wid >> 1) * 32;
    int gr4 = lane >> 2;
    int kc  = (lane & 3) * 2;

    float acc[2][4][4];
#pragma unroll
    for (int mt = 0; mt < 2; mt++)
#pragma unroll
        for (int nt = 0; nt < 4; nt++)
#pragma unroll
            for (int j = 0; j < 4; j++) acc[mt][nt][j] = 0.f;

    for (int c = 0; c < KC / 32; c++) {
        {
            int row = t >> 2, q = t & 3;
            int gr = row0 + row;
            uint4 vh = make_uint4(0u, 0u, 0u, 0u), vl = vh;
            if (gr < cnt) {
                size_t s = (size_t)gr * KC + c * 32 + q * 8;
                vh = *(const uint4*)&g_Ahi[s];
                vl = *(const uint4*)&g_Alo[s];
            }
            *(uint4*)&As[0][row * SA + q * 8] = vh;
            *(uint4*)&As[1][row * SA + q * 8] = vl;
        }
#pragma unroll
        for (int q2 = 0; q2 < 2; q2++) {
            int idx = t + q2 * 256;
            int h = idx >> 2, q = idx & 3;
            size_t s = (size_t)h * KC + c * 32 + q * 8;
            *(uint4*)&Bs[0][h * SA + q * 8] = *(const uint4*)&g_Bhi[s];
            *(uint4*)&Bs[1][h * SA + q * 8] = *(const uint4*)&g_Blo[s];
        }
        __syncthreads();

#pragma unroll
        for (int ks = 0; ks < 32; ks += 16) {
            unsigned ah[2][4], al[2][4], bh[4][2], bl[4][2];
#pragma unroll
            for (int mt = 0; mt < 2; mt++) {
                int r0 = wm + mt * 16 + gr4;
                ah[mt][0] = *(const unsigned*)&As[0][(r0    ) * SA + ks + kc];
                ah[mt][1] = *(const unsigned*)&As[0][(r0 + 8) * SA + ks + kc];
                ah[mt][2] = *(const unsigned*)&As[0][(r0    ) * SA + ks + kc + 8];
                ah[mt][3] = *(const unsigned*)&As[0][(r0 + 8) * SA + ks + kc + 8];
                al[mt][0] = *(const unsigned*)&As[1][(r0    ) * SA + ks + kc];
                al[mt][1] = *(const unsigned*)&As[1][(r0 + 8) * SA + ks + kc];
                al[mt][2] = *(const unsigned*)&As[1][(r0    ) * SA + ks + kc + 8];
                al[mt][3] = *(const unsigned*)&As[1][(r0 + 8) * SA + ks + kc + 8];
            }
#pragma unroll
            for (int nt = 0; nt < 4; nt++) {
                int n0 = wn + nt * 8 + gr4;
                bh[nt][0] = *(const unsigned*)&Bs[0][n0 * SA + ks + kc];
                bh[nt][1] = *(const unsigned*)&Bs[0][n0 * SA + ks + kc + 8];
                bl[nt][0] = *(const unsigned*)&Bs[1][n0 * SA + ks + kc];
                bl[nt][1] = *(const unsigned*)&Bs[1][n0 * SA + ks + kc + 8];
            }
#pragma unroll
            for (int mt = 0; mt < 2; mt++)
#pragma unroll
                for (int nt = 0; nt < 4; nt++) {
                    MMA16816(acc[mt][nt], ah[mt], bh[nt]);
                    MMA16816(acc[mt][nt], al[mt], bh[nt]);
                    MMA16816(acc[mt][nt], ah[mt], bl[nt]);
                }
        }
        __syncthreads();
    }

#pragma unroll
    for (int mt = 0; mt < 2; mt++) {
#pragma unroll
        for (int nt = 0; nt < 4; nt++) {
            int col = wn + nt * 8 + kc;
            float b0 = b1[col], b1v = b1[col + 1];
            int r0 = row0 + wm + mt * 16 + gr4;
            int r1 = r0 + 8;
            if (r0 < cnt) {
                float2 o;
                o.x = fmaxf(acc[mt][nt][0] + b0, 0.f);
                o.y = fmaxf(acc[mt][nt][1] + b1v, 0.f);
                *(float2*)&g_h[(size_t)r0 * 128 + col] = o;
            }
            if (r1 < cnt) {
                float2 o;
                o.x = fmaxf(acc[mt][nt][2] + b0, 0.f);
                o.y = fmaxf(acc[mt][nt][3] + b1v, 0.f);
                *(float2*)&g_h[(size_t)r1 * 128 + col] = o;
            }
        }
    }
}

// ------------------------------------------- kernel 6: layer-2 + pool + final
__global__ void __launch_bounds__(256) k_pool(const float* __restrict__ x,
                                              const int* __restrict__ pool,
                                              const int* __restrict__ ei,
                                              const float* __restrict__ W2,
                                              const float* __restrict__ root2,
                                              const float* __restrict__ b2,
                                              float* __restrict__ out) {
    __shared__ float cs[KC];
    __shared__ float red[256];
    __shared__ unsigned s_ticket;
    const float4* h4 = (const float4*)g_h;
    int p = pool[blockIdx.x];
    int t = threadIdx.x;
    int lane = t & 31, w = t >> 5;

    {
        int r = w;
        int ptr = g_head[r * NN + p];
        int c = 0;
        float4 acc = make_float4(0.f, 0.f, 0.f, 0.f);
        while (ptr) {
            int e = ptr - 1;
            int src = ei[e];
            int ci = g_cid[src];
            float4 hv = h4[ci * 32 + lane];
            acc.x += hv.x; acc.y += hv.y; acc.z += hv.z; acc.w += hv.w;
            c++;
            ptr = g_next[e];
        }
        if (c > 1) {
            float s = 1.0f / (float)c;
            acc.x *= s; acc.y *= s; acc.z *= s; acc.w *= s;
        }
        *(float4*)&cs[r * 128 + lane * 4] = acc;
    }
    if (t < 128) {
        int cp = g_cid[p];
        cs[1024 + t] = g_h[(size_t)cp * 128 + t];
    }
    __syncthreads();

    int j = t & 63, q = t >> 6;
    float s = 0.f;
    int k0 = q * 288;
#pragma unroll 4
    for (int k = k0; k < k0 + 288; k++) {
        float wv = (k < 1024) ? W2[k * 64 + j] : root2[(k - 1024) * 64 + j];
        s += cs[k] * wv;
    }
    red[t] = s;
    __syncthreads();
    if (t < 64) {
        float o = red[t] + red[t + 64] + red[t + 128] + red[t + 192] + b2[j];
        float wp = 4.f * x[p * 128 + 0] + x[p * 128 + 1] + 2.f * x[p * 128 + 2];
        g_part[blockIdx.x * 64 + j] = o * wp;
        if (j == 0) g_wp[blockIdx.x] = wp;
    }

    // ---- last-block final reduction ----
    __threadfence();
    __syncthreads();
    if (t == 0) s_ticket = atomicAdd(&g_done, 1);
    __syncthreads();
    if (s_ticket == NP - 1) {
        __threadfence();
        if (t < 64) {
            float acc = 0.f;
            for (int i = 0; i < NP; i++) acc += g_part[i * 64 + t];
            float ws = 0.f;
            for (int i = 0; i < NP; i++) ws += g_wp[i];
            out[t] = acc / (ws + 1e-9f);
        }
        if (t == 0) g_done = 0;   // reset for next replay
    }
}

// ---------------------------------------------------------------- launch
extern "C" void kernel_launch(void* const* d_in, const int* in_sizes, int n_in,
                              void* d_out, int out_size) {
    const float* x     = (const float*)d_in[0];
    const int*   ei    = (const int*)  d_in[1];
    const int*   et    = (const int*)  d_in[2];
    const int*   pool  = (const int*)  d_in[3];
    const float* W1    = (const float*)d_in[4];
    const float* root1 = (const float*)d_in[5];
    const float* b1    = (const float*)d_in[6];
    const float* W2    = (const float*)d_in[7];
    const float* root2 = (const float*)d_in[8];
    const float* b2    = (const float*)d_in[9];
    float* out = (float*)d_out;
    (void)in_sizes; (void)n_in; (void)out_size;

    k_mark_pool<<<1, NP>>>(pool);
    k_mark_ws  <<<NB_MS + NB_WS + NB_HC, 256>>>(ei, W1, root1);
    k_cb       <<<NB_CP + NB_MS, 256>>>(ei, et);
    k_agg1     <<<2048, 256>>>(x, ei);
    k_gemm1h   <<<CAP / 64, 256>>>(b1);
    k_pool     <<<NP, 256>>>(x, pool, ei, W2, root2, b2, out);
}